// round 16
// baseline (speedup 1.0000x reference)
#include <cuda_runtime.h>
#include <cuda_bf16.h>
#include <mma.h>
#include <cstdint>

using namespace nvcuda;
typedef __nv_bfloat16 bf16;

#define NB    32
#define NENC  512
#define DSEQ  1024
#define NHEAD 8
#define HDIM  128
#define MROWS (NB*NENC)      /* 16384 */
#define NQKV  (3*DSEQ)       /* 3072  */
#define NCAT  (2*DSEQ)       /* 2048  */
#define PGRID 296            /* persistent grid: 148 SMs x 2 CTAs */

// ---------------- scratch (device globals; no allocations allowed) ----------
__device__ bf16  g_xn  [MROWS*DSEQ];
__device__ bf16  g_qkv [MROWS*NQKV];
__device__ bf16  g_vc  [MROWS*NCAT];
__device__ bf16  g_win [NQKV*DSEQ];
__device__ bf16  g_wout[DSEQ*NCAT];
__device__ bf16  g_wm1a[HDIM*HDIM];
__device__ float g_aq[NB*NHEAD*NENC];
__device__ float g_ak[NB*NHEAD*NENC];
__device__ float g_cq[NB*NHEAD*HDIM];
__device__ float g_ck[NB*NHEAD*HDIM];
__device__ float g_pq[NB*NHEAD*4*HDIM];
__device__ float g_pk[NB*NHEAD*4*HDIM];

// ---------------- PTX helpers ------------------------------------------------
__device__ __forceinline__ uint32_t smem_u32(const void* p) {
    uint32_t a;
    asm("{ .reg .u64 t; cvta.to.shared.u64 t, %1; cvt.u32.u64 %0, t; }" : "=r"(a) : "l"(p));
    return a;
}
__device__ __forceinline__ void cp16(uint32_t dst, const void* src) {
    asm volatile("cp.async.cg.shared.global [%0], [%1], 16;" :: "r"(dst), "l"(src));
}
#define CP_COMMIT() asm volatile("cp.async.commit_group;" ::: "memory")
#define CP_WAIT0()  asm volatile("cp.async.wait_group 0;" ::: "memory")
#define CP_WAIT1()  asm volatile("cp.async.wait_group 1;" ::: "memory")

__device__ __forceinline__ void ldsm_x4(uint32_t& r0, uint32_t& r1, uint32_t& r2,
                                        uint32_t& r3, uint32_t addr) {
    asm volatile("ldmatrix.sync.aligned.m8n8.x4.shared.b16 {%0,%1,%2,%3}, [%4];"
                 : "=r"(r0), "=r"(r1), "=r"(r2), "=r"(r3) : "r"(addr));
}
__device__ __forceinline__ void mma16816(float* d, const uint32_t* a, const uint32_t* b) {
    asm volatile(
        "mma.sync.aligned.m16n8k16.row.col.f32.bf16.bf16.f32 "
        "{%0,%1,%2,%3},{%4,%5,%6,%7},{%8,%9},{%0,%1,%2,%3};"
        : "+f"(d[0]), "+f"(d[1]), "+f"(d[2]), "+f"(d[3])
        : "r"(a[0]), "r"(a[1]), "r"(a[2]), "r"(a[3]), "r"(b[0]), "r"(b[1]));
}

// ==== persistent mma.sync GEMM: 128x128 tile, 8 warps x (32x64), 3-stage =====
#define BM 128
#define BN 128
#define BKC 64
#define STAGES 3
#define STAGE_B ((BM + BN) * BKC * 2)            /* 32768 B */
#define GEMM_SMEM (STAGES * STAGE_B)             /* 98304 B */

template<int EPI>
__global__ void __launch_bounds__(256, 2) gemm_nt(
    const bf16* __restrict__ A, const bf16* __restrict__ Bm, int K,
    const float* __restrict__ bias, const float* __restrict__ resid,
    void* __restrict__ C, int N) {

    extern __shared__ __align__(16) char smem[];
    const uint32_t sBase = smem_u32(smem);

    const int tid  = threadIdx.x;
    const int warp = tid >> 5, lane = tid & 31;
    const int wm = warp >> 1, wn = warp & 1;
    const int KT = K / BKC;
    const int gridX = N / BN;
    const int nTiles = gridX * (MROWS / BM);

    const int lr = tid >> 3;
    const int lc = tid & 7;

    const int a_row = lane & 15;
    const int a_chk = lane >> 4;
    const int b_n   = (lane & 7) + ((lane >> 4) << 3);
    const int b_chk = (lane >> 3) & 1;

    for (int tile = blockIdx.x; tile < nTiles; tile += PGRID) {
        const int rowA0 = (tile / gridX) * BM;
        const int colB0 = (tile % gridX) * BN;

        auto load_stage = [&](int kt, int s) {
            const uint32_t st = sBase + s * STAGE_B;
            #pragma unroll
            for (int i = 0; i < 4; i++) {
                int row = lr + i * 32;
                uint32_t sw = ((uint32_t)(lc ^ (row & 7))) << 4;
                cp16(st + row * 128 + sw,
                     A + (size_t)(rowA0 + row) * K + kt * BKC + lc * 8);
                cp16(st + BM * 128 + row * 128 + sw,
                     Bm + (size_t)(colB0 + row) * K + kt * BKC + lc * 8);
            }
        };

        float acc[2][8][4];
        #pragma unroll
        for (int fm = 0; fm < 2; fm++)
            #pragma unroll
            for (int fn = 0; fn < 8; fn++)
                #pragma unroll
                for (int j = 0; j < 4; j++) acc[fm][fn][j] = 0.0f;

        load_stage(0, 0); CP_COMMIT();
        load_stage(1, 1); CP_COMMIT();

        for (int kt = 0; kt < KT; kt++) {
            if (kt + 1 < KT) { CP_WAIT1(); } else { CP_WAIT0(); }
            __syncthreads();
            if (kt + 2 < KT) { load_stage(kt + 2, (kt + 2) % STAGES); CP_COMMIT(); }

            const uint32_t stg = sBase + (kt % STAGES) * STAGE_B;
            const uint32_t aBase = stg + (wm * 32) * 128;
            const uint32_t bBase = stg + BM * 128 + (wn * 64) * 128;

            #pragma unroll
            for (int ks = 0; ks < 4; ks++) {
                uint32_t a[2][4];
                #pragma unroll
                for (int fm = 0; fm < 2; fm++) {
                    int r = fm * 16 + a_row;
                    uint32_t addr = aBase + r * 128
                                  + ((uint32_t)((ks * 2 + a_chk) ^ (r & 7)) << 4);
                    ldsm_x4(a[fm][0], a[fm][1], a[fm][2], a[fm][3], addr);
                }
                uint32_t b[8][2];
                #pragma unroll
                for (int fp = 0; fp < 4; fp++) {
                    int n = fp * 16 + b_n;
                    uint32_t addr = bBase + n * 128
                                  + ((uint32_t)((ks * 2 + b_chk) ^ (n & 7)) << 4);
                    ldsm_x4(b[2*fp][0], b[2*fp][1], b[2*fp+1][0], b[2*fp+1][1], addr);
                }
                #pragma unroll
                for (int fm = 0; fm < 2; fm++)
                    #pragma unroll
                    for (int fn = 0; fn < 8; fn++)
                        mma16816(acc[fm][fn], a[fm], b[fn]);
            }
        }
        __syncthreads();

        float* epiW = reinterpret_cast<float*>(smem) + warp * (16 * 68);
        const int gr0 = rowA0 + wm * 32;
        const int gc0 = colB0 + wn * 64;
        const int col = 2 * lane;
        const int erow = lane >> 2;
        const int ecol = (lane & 3) * 2;
        float2 bs = *reinterpret_cast<const float2*>(bias + gc0 + col);
        #pragma unroll
        for (int fm = 0; fm < 2; fm++) {
            #pragma unroll
            for (int fn = 0; fn < 8; fn++) {
                *reinterpret_cast<float2*>(epiW + erow * 68 + fn * 8 + ecol) =
                    make_float2(acc[fm][fn][0], acc[fm][fn][1]);
                *reinterpret_cast<float2*>(epiW + (erow + 8) * 68 + fn * 8 + ecol) =
                    make_float2(acc[fm][fn][2], acc[fm][fn][3]);
            }
            __syncwarp();
            #pragma unroll
            for (int rr = 0; rr < 16; rr++) {
                size_t grow = (size_t)(gr0 + fm * 16 + rr);
                float v0 = epiW[rr * 68 + col]     + bs.x;
                float v1 = epiW[rr * 68 + col + 1] + bs.y;
                if (EPI == 0) {
                    bf16 o[2] = {__float2bfloat16(v0), __float2bfloat16(v1)};
                    *reinterpret_cast<uint32_t*>(reinterpret_cast<bf16*>(C) + grow * N + gc0 + col) =
                        *reinterpret_cast<uint32_t*>(o);
                } else {
                    float2 rr2 = *reinterpret_cast<const float2*>(resid + grow * N + gc0 + col);
                    *reinterpret_cast<float2*>(reinterpret_cast<float*>(C) + grow * N + gc0 + col) =
                        make_float2(v0 + rr2.x, v1 + rr2.y);
                }
            }
            __syncwarp();
        }
        __syncthreads();   // epilogue smem reads done before next tile's cp.async
    }
}

// ---------------- prep: LayerNorm + all fp32->bf16 weight conversions -------
#define PREP_LN    2048
#define PREP_WIN   (PREP_LN + 3072)
#define PREP_WOUT  (PREP_WIN + 2048)
#define PREP_TOTAL (PREP_WOUT + 16)

__global__ void __launch_bounds__(256) prep_kernel(
    const float* __restrict__ x, const float* __restrict__ g,
    const float* __restrict__ b, bf16* __restrict__ xn,
    const float* __restrict__ w_in, const float* __restrict__ w_out,
    const float* __restrict__ w_m1a) {
    const int blk = blockIdx.x;
    if (blk < PREP_LN) {
        const int warp = threadIdx.x >> 5, lane = threadIdx.x & 31;
        const size_t row = (size_t)blk * 8 + warp;
        const float4* xr = reinterpret_cast<const float4*>(x + row * DSEQ);
        float4 v[8];
        float s = 0.f, s2 = 0.f;
        #pragma unroll
        for (int j = 0; j < 8; j++) {
            v[j] = xr[j * 32 + lane];
            s  += v[j].x + v[j].y + v[j].z + v[j].w;
            s2 += v[j].x*v[j].x + v[j].y*v[j].y + v[j].z*v[j].z + v[j].w*v[j].w;
        }
        #pragma unroll
        for (int o = 16; o > 0; o >>= 1) {
            s  += __shfl_xor_sync(0xffffffffu, s,  o);
            s2 += __shfl_xor_sync(0xffffffffu, s2, o);
        }
        float mean = s * (1.0f / DSEQ);
        float var  = s2 * (1.0f / DSEQ) - mean * mean;
        float rstd = rsqrtf(var + 1e-5f);
        uint2* orow = reinterpret_cast<uint2*>(xn + row * DSEQ);
        #pragma unroll
        for (int j = 0; j < 8; j++) {
            float4 gg = reinterpret_cast<const float4*>(g)[j * 32 + lane];
            float4 bb = reinterpret_cast<const float4*>(b)[j * 32 + lane];
            bf16 o[4];
            o[0] = __float2bfloat16((v[j].x - mean) * rstd * gg.x + bb.x);
            o[1] = __float2bfloat16((v[j].y - mean) * rstd * gg.y + bb.y);
            o[2] = __float2bfloat16((v[j].z - mean) * rstd * gg.z + bb.z);
            o[3] = __float2bfloat16((v[j].w - mean) * rstd * gg.w + bb.w);
            orow[j * 32 + lane] = *reinterpret_cast<uint2*>(o);
        }
        return;
    }
    const float* src; bf16* dst; int i;
    if (blk < PREP_WIN) {
        src = w_in;  dst = g_win;  i = (blk - PREP_LN) * 256 + threadIdx.x;
    } else if (blk < PREP_WOUT) {
        src = w_out; dst = g_wout; i = (blk - PREP_WIN) * 256 + threadIdx.x;
    } else {
        src = w_m1a; dst = g_wm1a; i = (blk - PREP_WOUT) * 256 + threadIdx.x;
    }
    float4 v = reinterpret_cast<const float4*>(src)[i];
    bf16 o[4] = {__float2bfloat16(v.x), __float2bfloat16(v.y),
                 __float2bfloat16(v.z), __float2bfloat16(v.w)};
    reinterpret_cast<uint2*>(dst)[i] = *reinterpret_cast<uint2*>(o);
}

// ---------------- mlp1 (+fused mlp2 partial): per-block (b,h), 128 n-rows ----
#define MLP1_SMEM 72192

__global__ void __launch_bounds__(256, 2) mlp1_kernel(
    const bf16* __restrict__ qkv,
    const float* __restrict__ b1a, const float* __restrict__ w1b,
    const float* __restrict__ b1b, const float* __restrict__ w2,
    float* __restrict__ aoutQ, float* __restrict__ aoutK,
    float* __restrict__ partQ, float* __restrict__ partK) {

    extern __shared__ __align__(16) char dsm[];
    bf16*  sA   = reinterpret_cast<bf16*>(dsm);
    bf16*  sB   = reinterpret_cast<bf16*>(dsm) + 128*136;
    float* sAcc = reinterpret_cast<float*>(dsm);
    float* sb   = reinterpret_cast<float*>(dsm + 69632);
    float* sw   = reinterpret_cast<float*>(dsm + 70144);
    float* sw2  = reinterpret_cast<float*>(dsm + 70656);
    float* ph   = reinterpret_cast<float*>(dsm + 71168);

    const int tid = threadIdx.x;
    const int warp = tid >> 5;
    const int wm = warp >> 2, wn = warp & 3;
    const int r0 = blockIdx.x * 128;
    const int off = blockIdx.y * 1024;
    const int n0 = r0 & 511;
    float* aout = blockIdx.y ? aoutK : aoutQ;
    float* part = blockIdx.y ? partK : partQ;

    if (tid < 128) {
        sb[tid]  = b1a[tid];
        sw[tid]  = w1b[tid];
        sw2[tid] = w2[n0 + tid];
    }
    #pragma unroll
    for (int i = 0; i < 8; i++) {
        int v = tid + 256 * i;
        int r = v >> 4, c = (v & 15) * 8;
        int gr = r0 + r;
        size_t base = ((size_t)(gr >> 12) * 512 + ((gr & 4095) >> 3)) * 3072
                    + ((gr & 7) << 7) + off;
        *reinterpret_cast<uint4*>(sA + r * 136 + c) =
            *reinterpret_cast<const uint4*>(qkv + base + c);
        *reinterpret_cast<uint4*>(sB + r * 136 + c) =
            *reinterpret_cast<const uint4*>(g_wm1a + r * 128 + c);
    }
    __syncthreads();

    wmma::fragment<wmma::accumulator, 16, 16, 16, float> acc[4][2];
    #pragma unroll
    for (int fm = 0; fm < 4; fm++)
        #pragma unroll
        for (int fn = 0; fn < 2; fn++) wmma::fill_fragment(acc[fm][fn], 0.0f);

    #pragma unroll
    for (int ks = 0; ks < 8; ks++) {
        wmma::fragment<wmma::matrix_a, 16, 16, 16, bf16, wmma::row_major> af[4];
        wmma::fragment<wmma::matrix_b, 16, 16, 16, bf16, wmma::col_major> bfr[2];
        #pragma unroll
        for (int fm = 0; fm < 4; fm++)
            wmma::load_matrix_sync(af[fm], sA + (wm * 64 + fm * 16) * 136 + ks * 16, 136);
        #pragma unroll
        for (int fn = 0; fn < 2; fn++)
            wmma::load_matrix_sync(bfr[fn], sB + (wn * 32 + fn * 16) * 136 + ks * 16, 136);
        #pragma unroll
        for (int fm = 0; fm < 4; fm++)
            #pragma unroll
            for (int fn = 0; fn < 2; fn++)
                wmma::mma_sync(acc[fm][fn], af[fm], bfr[fn], acc[fm][fn]);
    }

    // fused mlp2 partial: read sA before it is overwritten
    {
        const int d = tid & 127, half = tid >> 7;
        float ps = 0.f;
        const bf16* col = sA + (half * 64) * 136 + d;
        const float* wv = sw2 + half * 64;
        #pragma unroll 8
        for (int i = 0; i < 64; i++)
            ps += __bfloat162float(col[i * 136]) * wv[i];
        ph[tid] = ps;
    }
    __syncthreads();
    #pragma unroll
    for (int fm = 0; fm < 4; fm++)
        #pragma unroll
        for (int fn = 0; fn < 2; fn++)
            wmma::store_matrix_sync(sAcc + (wm * 64 + fm * 16) * 132 + wn * 32 + fn * 16,
                                    acc[fm][fn], 132, wmma::mem_row_major);
    __syncthreads();
    if (tid < 128) {
        float s = b1b[0];
        #pragma unroll 4
        for (int e = 0; e < 128; e++) {
            float v = sAcc[tid * 132 + e] + sb[e];
            s += fmaxf(v, 0.0f) * sw[e];
        }
        aout[r0 + tid] = s;
        part[((r0 >> 9) * 4 + ((r0 >> 7) & 3)) * 128 + tid] = ph[tid] + ph[tid + 128];
    }
}

// ---------------- mlp2 reduce: c = relu(sum 4 partials + b2) -----------------
__global__ void mlp2_red_kernel(const float* __restrict__ pQ, const float* __restrict__ pK,
                                const float* __restrict__ b2,
                                float* __restrict__ cq, float* __restrict__ ck) {
    int i = blockIdx.x * blockDim.x + threadIdx.x;
    int bh = i >> 7, d = i & 127;
    size_t base = (size_t)bh * 512 + d;
    float sq = 0.f, sk = 0.f;
    #pragma unroll
    for (int ns = 0; ns < 4; ns++) {
        sq += pQ[base + ns * 128];
        sk += pK[base + ns * 128];
    }
    float bb = b2[0];
    cq[i] = fmaxf(sq + bb, 0.0f);
    ck[i] = fmaxf(sk + bb, 0.0f);
}

// ---------------- build concat(v1, v2), 16B vectorized ----------------------
__global__ void __launch_bounds__(256) vcat_kernel(
    const bf16* __restrict__ qkv, bf16* __restrict__ vc,
    const float* __restrict__ aq, const float* __restrict__ ak,
    const float* __restrict__ cq, const float* __restrict__ ck) {
    int tid = blockIdx.x * blockDim.x + threadIdx.x;
    int b  = tid >> 16;
    int ii = (tid & 65535) << 3;
    int h = ii >> 16;
    int n = (ii >> 7) & 511;
    int d = ii & 127;
    int row = ii >> 10;
    int col = ii & 1023;
    const float scale = 1.0f / 256.0f;
    size_t qbase = ((size_t)b * 512 + row) * 3072;
    uint4 v8 = *reinterpret_cast<const uint4*>(qkv + qbase + 2048 + col);
    const bf16* vp = reinterpret_cast<const bf16*>(&v8);
    int bh = b * 8 + h;
    float a1 = aq[bh * 512 + n] * scale;
    float a2 = ak[bh * 512 + n] * scale;
    float4 c1a = *reinterpret_cast<const float4*>(ck + bh * 128 + d);
    float4 c1b = *reinterpret_cast<const float4*>(ck + bh * 128 + d + 4);
    float4 c2a = *reinterpret_cast<const float4*>(cq + bh * 128 + d);
    float4 c2b = *reinterpret_cast<const float4*>(cq + bh * 128 + d + 4);
    float cv1[8] = {c1a.x, c1a.y, c1a.z, c1a.w, c1b.x, c1b.y, c1b.z, c1b.w};
    float cv2[8] = {c2a.x, c2a.y, c2a.z, c2a.w, c2b.x, c2b.y, c2b.z, c2b.w};
    bf16 o1[8], o2[8];
    #pragma unroll
    for (int j = 0; j < 8; j++) {
        float vv = __bfloat162float(vp[j]);
        o1[j] = __float2bfloat16(a1 * cv1[j] * vv);
        o2[j] = __float2bfloat16(a2 * cv2[j] * vv);
    }
    size_t obase = ((size_t)b * 512 + row) * 2048;
    *reinterpret_cast<uint4*>(vc + obase + col)        = *reinterpret_cast<uint4*>(o1);
    *reinterpret_cast<uint4*>(vc + obase + 1024 + col) = *reinterpret_cast<uint4*>(o2);
}

// ---------------- launch --------------------------------------------------
extern "C" void kernel_launch(void* const* d_in, const int* in_sizes, int n_in,
                              void* d_out, int out_size) {
    const float* x     = (const float*)d_in[0];
    const float* ln_g  = (const float*)d_in[1];
    const float* ln_b  = (const float*)d_in[2];
    const float* w_in  = (const float*)d_in[3];
    const float* b_in  = (const float*)d_in[4];
    const float* w_m1a = (const float*)d_in[5];
    const float* b_m1a = (const float*)d_in[6];
    const float* w_m1b = (const float*)d_in[7];
    const float* b_m1b = (const float*)d_in[8];
    const float* w_m2  = (const float*)d_in[9];
    const float* b_m2  = (const float*)d_in[10];
    const float* w_out = (const float*)d_in[11];
    const float* b_out = (const float*)d_in[12];
    float* out = (float*)d_out;

    bf16 *xn, *qkv, *vc, *win, *wout;
    float *aq, *ak, *cq, *ck, *pq, *pk;
    cudaGetSymbolAddress((void**)&xn,   g_xn);
    cudaGetSymbolAddress((void**)&qkv,  g_qkv);
    cudaGetSymbolAddress((void**)&vc,   g_vc);
    cudaGetSymbolAddress((void**)&win,  g_win);
    cudaGetSymbolAddress((void**)&wout, g_wout);
    cudaGetSymbolAddress((void**)&aq,   g_aq);
    cudaGetSymbolAddress((void**)&ak,   g_ak);
    cudaGetSymbolAddress((void**)&cq,   g_cq);
    cudaGetSymbolAddress((void**)&ck,   g_ck);
    cudaGetSymbolAddress((void**)&pq,   g_pq);
    cudaGetSymbolAddress((void**)&pk,   g_pk);

    cudaFuncSetAttribute(mlp1_kernel, cudaFuncAttributeMaxDynamicSharedMemorySize, MLP1_SMEM);
    cudaFuncSetAttribute(gemm_nt<0>,  cudaFuncAttributeMaxDynamicSharedMemorySize, GEMM_SMEM);
    cudaFuncSetAttribute(gemm_nt<1>,  cudaFuncAttributeMaxDynamicSharedMemorySize, GEMM_SMEM);

    // 1) prep: LN + all weight conversions (single launch)
    prep_kernel<<<PREP_TOTAL, 256>>>(x, ln_g, ln_b, xn, w_in, w_out, w_m1a);
    // 2) QKV projection (persistent grid)
    gemm_nt<0><<<PGRID, 256, GEMM_SMEM>>>(xn, win, DSEQ, b_in, nullptr, qkv, NQKV);
    // 3) mlp1 over q and k + fused mlp2 partials
    mlp1_kernel<<<dim3(1024, 2), 256, MLP1_SMEM>>>(qkv, b_m1a, w_m1b, b_m1b, w_m2,
                                                   aq, ak, pq, pk);
    // 4) mlp2 reduce
    mlp2_red_kernel<<<(NB * NHEAD * HDIM) / 256, 256>>>(pq, pk, b_m2, cq, ck);
    // 5) rank-1 scaled V -> concat buffer
    vcat_kernel<<<8192, 256>>>(qkv, vc, aq, ak, cq, ck);
    // 6) output projection + bias + residual (persistent grid)
    gemm_nt<1><<<PGRID, 256, GEMM_SMEM>>>(vc, wout, NCAT, b_out, x, out, DSEQ);
}

// round 17
// speedup vs baseline: 1.0799x; 1.0799x over previous
#include <cuda_runtime.h>
#include <cuda_bf16.h>
#include <mma.h>
#include <cstdint>

using namespace nvcuda;
typedef __nv_bfloat16 bf16;

#define NB    32
#define NENC  512
#define DSEQ  1024
#define NHEAD 8
#define HDIM  128
#define MROWS (NB*NENC)      /* 16384 */
#define NQKV  (3*DSEQ)       /* 3072  */
#define NCAT  (2*DSEQ)       /* 2048  */

// ---------------- scratch (device globals; no allocations allowed) ----------
__device__ bf16  g_xn  [MROWS*DSEQ];
__device__ bf16  g_qkv [MROWS*NQKV];
__device__ bf16  g_vc  [MROWS*NCAT];
__device__ bf16  g_win [NQKV*DSEQ];
__device__ bf16  g_wout[DSEQ*NCAT];
__device__ bf16  g_wm1a[HDIM*HDIM];
__device__ float g_aq[NB*NHEAD*NENC];
__device__ float g_ak[NB*NHEAD*NENC];
__device__ float g_cq[NB*NHEAD*HDIM];
__device__ float g_ck[NB*NHEAD*HDIM];
__device__ float g_pq[NB*NHEAD*4*HDIM];
__device__ float g_pk[NB*NHEAD*4*HDIM];

// ---------------- PTX helpers ------------------------------------------------
__device__ __forceinline__ uint32_t smem_u32(const void* p) {
    uint32_t a;
    asm("{ .reg .u64 t; cvta.to.shared.u64 t, %1; cvt.u32.u64 %0, t; }" : "=r"(a) : "l"(p));
    return a;
}
__device__ __forceinline__ void cp16(uint32_t dst, const void* src) {
    asm volatile("cp.async.cg.shared.global [%0], [%1], 16;" :: "r"(dst), "l"(src));
}
#define CP_COMMIT() asm volatile("cp.async.commit_group;" ::: "memory")
#define CP_WAIT0()  asm volatile("cp.async.wait_group 0;" ::: "memory")
#define CP_WAIT1()  asm volatile("cp.async.wait_group 1;" ::: "memory")

__device__ __forceinline__ void ldsm_x4(uint32_t& r0, uint32_t& r1, uint32_t& r2,
                                        uint32_t& r3, uint32_t addr) {
    asm volatile("ldmatrix.sync.aligned.m8n8.x4.shared.b16 {%0,%1,%2,%3}, [%4];"
                 : "=r"(r0), "=r"(r1), "=r"(r2), "=r"(r3) : "r"(addr));
}
__device__ __forceinline__ void mma16816(float* d, const uint32_t* a, const uint32_t* b) {
    asm volatile(
        "mma.sync.aligned.m16n8k16.row.col.f32.bf16.bf16.f32 "
        "{%0,%1,%2,%3},{%4,%5,%6,%7},{%8,%9},{%0,%1,%2,%3};"
        : "+f"(d[0]), "+f"(d[1]), "+f"(d[2]), "+f"(d[3])
        : "r"(a[0]), "r"(a[1]), "r"(a[2]), "r"(a[3]), "r"(b[0]), "r"(b[1]));
}

// ========== mma.sync GEMM: 128x128 tile, 8 warps x (32x64), 3-stage ==========
#define BM 128
#define BN 128
#define BKC 64
#define STAGES 3
#define STAGE_B ((BM + BN) * BKC * 2)            /* 32768 B */
#define GEMM_SMEM (STAGES * STAGE_B)             /* 98304 B */

template<int EPI>
__global__ void __launch_bounds__(256, 2) gemm_nt(
    const bf16* __restrict__ A, const bf16* __restrict__ Bm, int K,
    const float* __restrict__ bias, const float* __restrict__ resid,
    void* __restrict__ C, int N) {

    extern __shared__ __align__(16) char smem[];
    const uint32_t sBase = smem_u32(smem);

    const int tid  = threadIdx.x;
    const int warp = tid >> 5, lane = tid & 31;
    const int wm = warp >> 1, wn = warp & 1;
    const int rowA0 = blockIdx.y * BM;
    const int colB0 = blockIdx.x * BN;
    const int KT = K / BKC;

    const int lr = tid >> 3;
    const int lc = tid & 7;

    auto load_stage = [&](int kt, int s) {
        const uint32_t st = sBase + s * STAGE_B;
        #pragma unroll
        for (int i = 0; i < 4; i++) {
            int row = lr + i * 32;
            uint32_t sw = ((uint32_t)(lc ^ (row & 7))) << 4;
            cp16(st + row * 128 + sw,
                 A + (size_t)(rowA0 + row) * K + kt * BKC + lc * 8);
            cp16(st + BM * 128 + row * 128 + sw,
                 Bm + (size_t)(colB0 + row) * K + kt * BKC + lc * 8);
        }
    };

    float acc[2][8][4];
    #pragma unroll
    for (int fm = 0; fm < 2; fm++)
        #pragma unroll
        for (int fn = 0; fn < 8; fn++)
            #pragma unroll
            for (int j = 0; j < 4; j++) acc[fm][fn][j] = 0.0f;

    load_stage(0, 0); CP_COMMIT();
    load_stage(1, 1); CP_COMMIT();

    const int a_row = lane & 15;
    const int a_chk = lane >> 4;
    const int b_n   = (lane & 7) + ((lane >> 4) << 3);
    const int b_chk = (lane >> 3) & 1;

    for (int kt = 0; kt < KT; kt++) {
        if (kt + 1 < KT) { CP_WAIT1(); } else { CP_WAIT0(); }
        __syncthreads();
        if (kt + 2 < KT) { load_stage(kt + 2, (kt + 2) % STAGES); CP_COMMIT(); }

        const uint32_t stg = sBase + (kt % STAGES) * STAGE_B;
        const uint32_t aBase = stg + (wm * 32) * 128;
        const uint32_t bBase = stg + BM * 128 + (wn * 64) * 128;

        #pragma unroll
        for (int ks = 0; ks < 4; ks++) {
            uint32_t a[2][4];
            #pragma unroll
            for (int fm = 0; fm < 2; fm++) {
                int r = fm * 16 + a_row;
                uint32_t addr = aBase + r * 128
                              + ((uint32_t)((ks * 2 + a_chk) ^ (r & 7)) << 4);
                ldsm_x4(a[fm][0], a[fm][1], a[fm][2], a[fm][3], addr);
            }
            uint32_t b[8][2];
            #pragma unroll
            for (int fp = 0; fp < 4; fp++) {
                int n = fp * 16 + b_n;
                uint32_t addr = bBase + n * 128
                              + ((uint32_t)((ks * 2 + b_chk) ^ (n & 7)) << 4);
                ldsm_x4(b[2*fp][0], b[2*fp][1], b[2*fp+1][0], b[2*fp+1][1], addr);
            }
            #pragma unroll
            for (int fm = 0; fm < 2; fm++)
                #pragma unroll
                for (int fn = 0; fn < 8; fn++)
                    mma16816(acc[fm][fn], a[fm], b[fn]);
        }
    }
    __syncthreads();

    float* epiW = reinterpret_cast<float*>(smem) + warp * (16 * 68);
    const int gr0 = rowA0 + wm * 32;
    const int gc0 = colB0 + wn * 64;
    const int col = 2 * lane;
    const int erow = lane >> 2;
    const int ecol = (lane & 3) * 2;
    float2 bs = *reinterpret_cast<const float2*>(bias + gc0 + col);
    #pragma unroll
    for (int fm = 0; fm < 2; fm++) {
        #pragma unroll
        for (int fn = 0; fn < 8; fn++) {
            *reinterpret_cast<float2*>(epiW + erow * 68 + fn * 8 + ecol) =
                make_float2(acc[fm][fn][0], acc[fm][fn][1]);
            *reinterpret_cast<float2*>(epiW + (erow + 8) * 68 + fn * 8 + ecol) =
                make_float2(acc[fm][fn][2], acc[fm][fn][3]);
        }
        __syncwarp();
        #pragma unroll
        for (int rr = 0; rr < 16; rr++) {
            size_t grow = (size_t)(gr0 + fm * 16 + rr);
            float v0 = epiW[rr * 68 + col]     + bs.x;
            float v1 = epiW[rr * 68 + col + 1] + bs.y;
            if (EPI == 0) {
                bf16 o[2] = {__float2bfloat16(v0), __float2bfloat16(v1)};
                *reinterpret_cast<uint32_t*>(reinterpret_cast<bf16*>(C) + grow * N + gc0 + col) =
                    *reinterpret_cast<uint32_t*>(o);
            } else {
                float2 rr2 = *reinterpret_cast<const float2*>(resid + grow * N + gc0 + col);
                *reinterpret_cast<float2*>(reinterpret_cast<float*>(C) + grow * N + gc0 + col) =
                    make_float2(v0 + rr2.x, v1 + rr2.y);
            }
        }
        __syncwarp();
    }
}

// ---------------- prep: LayerNorm + all fp32->bf16 weight conversions -------
#define PREP_LN    2048
#define PREP_WIN   (PREP_LN + 3072)
#define PREP_WOUT  (PREP_WIN + 2048)
#define PREP_TOTAL (PREP_WOUT + 16)

__global__ void __launch_bounds__(256) prep_kernel(
    const float* __restrict__ x, const float* __restrict__ g,
    const float* __restrict__ b, bf16* __restrict__ xn,
    const float* __restrict__ w_in, const float* __restrict__ w_out,
    const float* __restrict__ w_m1a) {
    const int blk = blockIdx.x;
    if (blk < PREP_LN) {
        const int warp = threadIdx.x >> 5, lane = threadIdx.x & 31;
        const size_t row = (size_t)blk * 8 + warp;
        const float4* xr = reinterpret_cast<const float4*>(x + row * DSEQ);
        float4 v[8];
        float s = 0.f, s2 = 0.f;
        #pragma unroll
        for (int j = 0; j < 8; j++) {
            v[j] = xr[j * 32 + lane];
            s  += v[j].x + v[j].y + v[j].z + v[j].w;
            s2 += v[j].x*v[j].x + v[j].y*v[j].y + v[j].z*v[j].z + v[j].w*v[j].w;
        }
        #pragma unroll
        for (int o = 16; o > 0; o >>= 1) {
            s  += __shfl_xor_sync(0xffffffffu, s,  o);
            s2 += __shfl_xor_sync(0xffffffffu, s2, o);
        }
        float mean = s * (1.0f / DSEQ);
        float var  = s2 * (1.0f / DSEQ) - mean * mean;
        float rstd = rsqrtf(var + 1e-5f);
        uint2* orow = reinterpret_cast<uint2*>(xn + row * DSEQ);
        #pragma unroll
        for (int j = 0; j < 8; j++) {
            float4 gg = reinterpret_cast<const float4*>(g)[j * 32 + lane];
            float4 bb = reinterpret_cast<const float4*>(b)[j * 32 + lane];
            bf16 o[4];
            o[0] = __float2bfloat16((v[j].x - mean) * rstd * gg.x + bb.x);
            o[1] = __float2bfloat16((v[j].y - mean) * rstd * gg.y + bb.y);
            o[2] = __float2bfloat16((v[j].z - mean) * rstd * gg.z + bb.z);
            o[3] = __float2bfloat16((v[j].w - mean) * rstd * gg.w + bb.w);
            orow[j * 32 + lane] = *reinterpret_cast<uint2*>(o);
        }
        return;
    }
    const float* src; bf16* dst; int i;
    if (blk < PREP_WIN) {
        src = w_in;  dst = g_win;  i = (blk - PREP_LN) * 256 + threadIdx.x;
    } else if (blk < PREP_WOUT) {
        src = w_out; dst = g_wout; i = (blk - PREP_WIN) * 256 + threadIdx.x;
    } else {
        src = w_m1a; dst = g_wm1a; i = (blk - PREP_WOUT) * 256 + threadIdx.x;
    }
    float4 v = reinterpret_cast<const float4*>(src)[i];
    bf16 o[4] = {__float2bfloat16(v.x), __float2bfloat16(v.y),
                 __float2bfloat16(v.z), __float2bfloat16(v.w)};
    reinterpret_cast<uint2*>(dst)[i] = *reinterpret_cast<uint2*>(o);
}

// ---------------- mlp1 (+fused mlp2 partial): per-block (b,h), 128 n-rows ----
// smem: sA/sAcc | sB | sb | sw | sw2 | ph (mlp2 halves) | ph2 (mlp1 halves)
#define MLP1_SMEM 73216

__global__ void __launch_bounds__(256, 2) mlp1_kernel(
    const bf16* __restrict__ qkv,
    const float* __restrict__ b1a, const float* __restrict__ w1b,
    const float* __restrict__ b1b, const float* __restrict__ w2,
    float* __restrict__ aoutQ, float* __restrict__ aoutK,
    float* __restrict__ partQ, float* __restrict__ partK) {

    extern __shared__ __align__(16) char dsm[];
    bf16*  sA   = reinterpret_cast<bf16*>(dsm);            // [128][136]
    bf16*  sB   = reinterpret_cast<bf16*>(dsm) + 128*136;  // [128][136]
    float* sAcc = reinterpret_cast<float*>(dsm);           // reuse (128x132)
    float* sb   = reinterpret_cast<float*>(dsm + 69632);
    float* sw   = reinterpret_cast<float*>(dsm + 70144);
    float* sw2  = reinterpret_cast<float*>(dsm + 70656);
    float* ph   = reinterpret_cast<float*>(dsm + 71168);   // 256 f32
    float* ph2  = reinterpret_cast<float*>(dsm + 72192);   // 256 f32

    const int tid = threadIdx.x;
    const int warp = tid >> 5;
    const int wm = warp >> 2, wn = warp & 3;
    const int r0 = blockIdx.x * 128;
    const int off = blockIdx.y * 1024;
    const int n0 = r0 & 511;
    float* aout = blockIdx.y ? aoutK : aoutQ;
    float* part = blockIdx.y ? partK : partQ;

    if (tid < 128) {
        sb[tid]  = b1a[tid];
        sw[tid]  = w1b[tid];
        sw2[tid] = w2[n0 + tid];
    }
    #pragma unroll
    for (int i = 0; i < 8; i++) {
        int v = tid + 256 * i;
        int r = v >> 4, c = (v & 15) * 8;
        int gr = r0 + r;
        size_t base = ((size_t)(gr >> 12) * 512 + ((gr & 4095) >> 3)) * 3072
                    + ((gr & 7) << 7) + off;
        *reinterpret_cast<uint4*>(sA + r * 136 + c) =
            *reinterpret_cast<const uint4*>(qkv + base + c);
        *reinterpret_cast<uint4*>(sB + r * 136 + c) =
            *reinterpret_cast<const uint4*>(g_wm1a + r * 128 + c);
    }
    __syncthreads();

    wmma::fragment<wmma::accumulator, 16, 16, 16, float> acc[4][2];
    #pragma unroll
    for (int fm = 0; fm < 4; fm++)
        #pragma unroll
        for (int fn = 0; fn < 2; fn++) wmma::fill_fragment(acc[fm][fn], 0.0f);

    #pragma unroll
    for (int ks = 0; ks < 8; ks++) {
        wmma::fragment<wmma::matrix_a, 16, 16, 16, bf16, wmma::row_major> af[4];
        wmma::fragment<wmma::matrix_b, 16, 16, 16, bf16, wmma::col_major> bfr[2];
        #pragma unroll
        for (int fm = 0; fm < 4; fm++)
            wmma::load_matrix_sync(af[fm], sA + (wm * 64 + fm * 16) * 136 + ks * 16, 136);
        #pragma unroll
        for (int fn = 0; fn < 2; fn++)
            wmma::load_matrix_sync(bfr[fn], sB + (wn * 32 + fn * 16) * 136 + ks * 16, 136);
        #pragma unroll
        for (int fm = 0; fm < 4; fm++)
            #pragma unroll
            for (int fn = 0; fn < 2; fn++)
                wmma::mma_sync(acc[fm][fn], af[fm], bfr[fn], acc[fm][fn]);
    }

    // fused mlp2 partial: read sA before it is overwritten
    {
        const int d = tid & 127, half = tid >> 7;
        float ps = 0.f;
        const bf16* col = sA + (half * 64) * 136 + d;
        const float* wv = sw2 + half * 64;
        #pragma unroll 8
        for (int i = 0; i < 64; i++)
            ps += __bfloat162float(col[i * 136]) * wv[i];
        ph[tid] = ps;
    }
    __syncthreads();
    #pragma unroll
    for (int fm = 0; fm < 4; fm++)
        #pragma unroll
        for (int fn = 0; fn < 2; fn++)
            wmma::store_matrix_sync(sAcc + (wm * 64 + fm * 16) * 132 + wn * 32 + fn * 16,
                                    acc[fm][fn], 132, wmma::mem_row_major);
    __syncthreads();

    // mlp1 reduction split across all 256 threads (64 elems each)
    {
        const int row = tid & 127, half = tid >> 7;
        const float* ar = sAcc + row * 132 + half * 64;
        const float* bb = sb + half * 64;
        const float* ww = sw + half * 64;
        float s = 0.f;
        #pragma unroll 8
        for (int e = 0; e < 64; e++)
            s += fmaxf(ar[e] + bb[e], 0.0f) * ww[e];
        ph2[tid] = s;
    }
    __syncthreads();
    if (tid < 128) {
        aout[r0 + tid] = ph2[tid] + ph2[tid + 128] + b1b[0];
        part[((r0 >> 9) * 4 + ((r0 >> 7) & 3)) * 128 + tid] = ph[tid] + ph[tid + 128];
    }
}

// ---------------- mlp2 reduce: c = relu(sum 4 partials + b2) -----------------
__global__ void mlp2_red_kernel(const float* __restrict__ pQ, const float* __restrict__ pK,
                                const float* __restrict__ b2,
                                float* __restrict__ cq, float* __restrict__ ck) {
    int i = blockIdx.x * blockDim.x + threadIdx.x;
    int bh = i >> 7, d = i & 127;
    size_t base = (size_t)bh * 512 + d;
    float sq = 0.f, sk = 0.f;
    #pragma unroll
    for (int ns = 0; ns < 4; ns++) {
        sq += pQ[base + ns * 128];
        sk += pK[base + ns * 128];
    }
    float bb = b2[0];
    cq[i] = fmaxf(sq + bb, 0.0f);
    ck[i] = fmaxf(sk + bb, 0.0f);
}

// ---------------- build concat(v1, v2), 16B vectorized ----------------------
__global__ void __launch_bounds__(256) vcat_kernel(
    const bf16* __restrict__ qkv, bf16* __restrict__ vc,
    const float* __restrict__ aq, const float* __restrict__ ak,
    const float* __restrict__ cq, const float* __restrict__ ck) {
    int tid = blockIdx.x * blockDim.x + threadIdx.x;
    int b  = tid >> 16;
    int ii = (tid & 65535) << 3;
    int h = ii >> 16;
    int n = (ii >> 7) & 511;
    int d = ii & 127;
    int row = ii >> 10;
    int col = ii & 1023;
    const float scale = 1.0f / 256.0f;
    size_t qbase = ((size_t)b * 512 + row) * 3072;
    uint4 v8 = *reinterpret_cast<const uint4*>(qkv + qbase + 2048 + col);
    const bf16* vp = reinterpret_cast<const bf16*>(&v8);
    int bh = b * 8 + h;
    float a1 = aq[bh * 512 + n] * scale;
    float a2 = ak[bh * 512 + n] * scale;
    float4 c1a = *reinterpret_cast<const float4*>(ck + bh * 128 + d);
    float4 c1b = *reinterpret_cast<const float4*>(ck + bh * 128 + d + 4);
    float4 c2a = *reinterpret_cast<const float4*>(cq + bh * 128 + d);
    float4 c2b = *reinterpret_cast<const float4*>(cq + bh * 128 + d + 4);
    float cv1[8] = {c1a.x, c1a.y, c1a.z, c1a.w, c1b.x, c1b.y, c1b.z, c1b.w};
    float cv2[8] = {c2a.x, c2a.y, c2a.z, c2a.w, c2b.x, c2b.y, c2b.z, c2b.w};
    bf16 o1[8], o2[8];
    #pragma unroll
    for (int j = 0; j < 8; j++) {
        float vv = __bfloat162float(vp[j]);
        o1[j] = __float2bfloat16(a1 * cv1[j] * vv);
        o2[j] = __float2bfloat16(a2 * cv2[j] * vv);
    }
    size_t obase = ((size_t)b * 512 + row) * 2048;
    *reinterpret_cast<uint4*>(vc + obase + col)        = *reinterpret_cast<uint4*>(o1);
    *reinterpret_cast<uint4*>(vc + obase + 1024 + col) = *reinterpret_cast<uint4*>(o2);
}

// ---------------- launch --------------------------------------------------
extern "C" void kernel_launch(void* const* d_in, const int* in_sizes, int n_in,
                              void* d_out, int out_size) {
    const float* x     = (const float*)d_in[0];
    const float* ln_g  = (const float*)d_in[1];
    const float* ln_b  = (const float*)d_in[2];
    const float* w_in  = (const float*)d_in[3];
    const float* b_in  = (const float*)d_in[4];
    const float* w_m1a = (const float*)d_in[5];
    const float* b_m1a = (const float*)d_in[6];
    const float* w_m1b = (const float*)d_in[7];
    const float* b_m1b = (const float*)d_in[8];
    const float* w_m2  = (const float*)d_in[9];
    const float* b_m2  = (const float*)d_in[10];
    const float* w_out = (const float*)d_in[11];
    const float* b_out = (const float*)d_in[12];
    float* out = (float*)d_out;

    bf16 *xn, *qkv, *vc, *win, *wout;
    float *aq, *ak, *cq, *ck, *pq, *pk;
    cudaGetSymbolAddress((void**)&xn,   g_xn);
    cudaGetSymbolAddress((void**)&qkv,  g_qkv);
    cudaGetSymbolAddress((void**)&vc,   g_vc);
    cudaGetSymbolAddress((void**)&win,  g_win);
    cudaGetSymbolAddress((void**)&wout, g_wout);
    cudaGetSymbolAddress((void**)&aq,   g_aq);
    cudaGetSymbolAddress((void**)&ak,   g_ak);
    cudaGetSymbolAddress((void**)&cq,   g_cq);
    cudaGetSymbolAddress((void**)&ck,   g_ck);
    cudaGetSymbolAddress((void**)&pq,   g_pq);
    cudaGetSymbolAddress((void**)&pk,   g_pk);

    cudaFuncSetAttribute(mlp1_kernel, cudaFuncAttributeMaxDynamicSharedMemorySize, MLP1_SMEM);
    cudaFuncSetAttribute(gemm_nt<0>,  cudaFuncAttributeMaxDynamicSharedMemorySize, GEMM_SMEM);
    cudaFuncSetAttribute(gemm_nt<1>,  cudaFuncAttributeMaxDynamicSharedMemorySize, GEMM_SMEM);

    // 1) prep: LN + all weight conversions (single launch)
    prep_kernel<<<PREP_TOTAL, 256>>>(x, ln_g, ln_b, xn, w_in, w_out, w_m1a);
    // 2) QKV projection
    gemm_nt<0><<<dim3(NQKV / BN, MROWS / BM), 256, GEMM_SMEM>>>(xn, win, DSEQ, b_in, nullptr, qkv, NQKV);
    // 3) mlp1 over q and k + fused mlp2 partials
    mlp1_kernel<<<dim3(1024, 2), 256, MLP1_SMEM>>>(qkv, b_m1a, w_m1b, b_m1b, w_m2,
                                                   aq, ak, pq, pk);
    // 4) mlp2 reduce
    mlp2_red_kernel<<<(NB * NHEAD * HDIM) / 256, 256>>>(pq, pk, b_m2, cq, ck);
    // 5) rank-1 scaled V -> concat buffer
    vcat_kernel<<<8192, 256>>>(qkv, vc, aq, ak, cq, ck);
    // 6) output projection + bias + residual
    gemm_nt<1><<<dim3(DSEQ / BN, MROWS / BM), 256, GEMM_SMEM>>>(vc, wout, NCAT, b_out, x, out, DSEQ);
}